// round 11
// baseline (speedup 1.0000x reference)
#include <cuda_runtime.h>

// SegmenterTensorFlow: windowed framing + overlap-add reconstruction.
// B=8, N=4194304, seg=1024, hop=512 -> NSEG=8191, out_len=N.
//
// d_out layout: X [B, NSEG, SEG] followed by x_rec [B, N].
//
// hop = seg/2 => each sample n (s0=n>>9, m=n&511) lies in exactly two segments:
//   X[b, s0,   m    ]  (invalid when s0 == NSEG)
//   X[b, s0-1, m+512]  (invalid when s0 == 0)
// x_rec[b,n] = x[b,n] * (v0*aw[m]*sw[m] + v1*aw[m+512]*sw[m+512]).
//
// R11 (final): best-of-session combination — R1's 256-thread flat launch
// (best kernel dur: 78.24us) with R9's 32-bit index arithmetic (best bench:
// 81.54us, 35 regs). Ten rounds established the workload is pinned at the
// mixed-stream DRAM ceiling (~6.1 TB/s for 1 read : 3 write, 536.8 MB
// mandatory traffic); cache policy, MLP, occupancy, phase-resident windows,
// and launch shape were all proven neutral-or-worse.

#define BB   8
#define NN   4194304u
#define SEG  1024u
#define HOP  512u
#define NSEG 8191u

__global__ __launch_bounds__(256)
void seg_olap_kernel(const float* __restrict__ x,
                     const float* __restrict__ aw,
                     const float* __restrict__ sw,
                     float* __restrict__ Xout,
                     float* __restrict__ rec)
{
    unsigned t = blockIdx.x * blockDim.x + threadIdx.x;   // < 2^23
    unsigned i = t << 2;                                  // element index, < 2^25

    unsigned b  = i >> 22;                                // N = 2^22
    unsigned n  = i & (NN - 1u);
    unsigned m  = n & (HOP - 1u);                         // mod-512 phase (vec-aligned)
    unsigned s0 = n >> 9;

    const bool v0 = (s0 < NSEG);                          // segment s0, offset m
    const bool v1 = (s0 >= 1u);                           // segment s0-1, offset m+512

    float4 xv  = *reinterpret_cast<const float4*>(x + i);
    float4 awl = *reinterpret_cast<const float4*>(aw + m);
    float4 awh = *reinterpret_cast<const float4*>(aw + m + HOP);
    float4 swl = *reinterpret_cast<const float4*>(sw + m);
    float4 swh = *reinterpret_cast<const float4*>(sw + m + HOP);

    // X writes (coalesced: consecutive n -> consecutive j within a segment row)
    if (v0) {
        float4 lo;
        lo.x = xv.x * awl.x; lo.y = xv.y * awl.y;
        lo.z = xv.z * awl.z; lo.w = xv.w * awl.w;
        unsigned off = (b * NSEG + s0) * SEG + m;         // < 2^26
        *reinterpret_cast<float4*>(Xout + off) = lo;
    }
    if (v1) {
        float4 hi;
        hi.x = xv.x * awh.x; hi.y = xv.y * awh.y;
        hi.z = xv.z * awh.z; hi.w = xv.w * awh.w;
        unsigned off = (b * NSEG + (s0 - 1u)) * SEG + (m + HOP);
        *reinterpret_cast<float4*>(Xout + off) = hi;
    }

    // overlap-add collapses to pointwise weight
    float w0 = v0 ? 1.0f : 0.0f;
    float w1 = v1 ? 1.0f : 0.0f;
    float4 r;
    r.x = xv.x * (w0 * awl.x * swl.x + w1 * awh.x * swh.x);
    r.y = xv.y * (w0 * awl.y * swl.y + w1 * awh.y * swh.y);
    r.z = xv.z * (w0 * awl.z * swl.z + w1 * awh.z * swh.z);
    r.w = xv.w * (w0 * awl.w * swl.w + w1 * awh.w * swh.w);
    *reinterpret_cast<float4*>(rec + i) = r;
}

extern "C" void kernel_launch(void* const* d_in, const int* in_sizes, int n_in,
                              void* d_out, int out_size)
{
    const float* x  = (const float*)d_in[0];
    const float* aw = (const float*)d_in[1];
    const float* sw = (const float*)d_in[2];

    float* Xout = (float*)d_out;
    float* rec  = Xout + (size_t)BB * NSEG * SEG;

    const unsigned total_vec4 = (BB * NN) / 4u;           // 8,388,608 (exact multiple)
    const unsigned threads = 256;
    const unsigned blocks = total_vec4 / threads;         // 32768, no remainder

    seg_olap_kernel<<<blocks, threads>>>(x, aw, sw, Xout, rec);
}

// round 12
// speedup vs baseline: 1.0075x; 1.0075x over previous
#include <cuda_runtime.h>

// SegmenterTensorFlow: windowed framing + overlap-add reconstruction.
// B=8, N=4194304, seg=1024, hop=512 -> NSEG=8191, out_len=N.
//
// d_out layout: X [B, NSEG, SEG] followed by x_rec [B, N].
//
// hop = seg/2 => each sample n (s0=n>>9, m=n&511) lies in exactly two segments:
//   X[b, s0,   m    ]  (invalid when s0 == NSEG)
//   X[b, s0-1, m+512]  (invalid when s0 == 0)
// x_rec[b,n] = x[b,n] * (v0*aw[m]*sw[m] + v1*aw[m+512]*sw[m+512]).
//
// FINAL (== R9, best measured: 81.54us bench / 79.2us kernel, 35 regs):
// flat 1D launch, 512-thread blocks, one float4 per thread, all index
// arithmetic in 32-bit. Eleven rounds established the workload is pinned
// at the mixed-stream DRAM ceiling (~6.1 TB/s for 1 read : 3 write,
// 536.8 MB mandatory traffic => ~78us kernel floor). Cache policies
// (evict-first/evict-last/fractional), MLP, occupancy, phase-resident
// windows, and launch geometry were all measured neutral-or-worse.

#define BB   8
#define NN   4194304u
#define SEG  1024u
#define HOP  512u
#define NSEG 8191u

__global__ __launch_bounds__(512)
void seg_olap_kernel(const float* __restrict__ x,
                     const float* __restrict__ aw,
                     const float* __restrict__ sw,
                     float* __restrict__ Xout,
                     float* __restrict__ rec)
{
    unsigned t = blockIdx.x * blockDim.x + threadIdx.x;   // < 2^23
    unsigned i = t << 2;                                  // element index, < 2^25

    unsigned b  = i >> 22;                                // N = 2^22
    unsigned n  = i & (NN - 1u);
    unsigned m  = n & (HOP - 1u);                         // mod-512 phase (vec-aligned)
    unsigned s0 = n >> 9;

    const bool v0 = (s0 < NSEG);                          // segment s0, offset m
    const bool v1 = (s0 >= 1u);                           // segment s0-1, offset m+512

    float4 xv  = *reinterpret_cast<const float4*>(x + i);
    float4 awl = *reinterpret_cast<const float4*>(aw + m);
    float4 awh = *reinterpret_cast<const float4*>(aw + m + HOP);
    float4 swl = *reinterpret_cast<const float4*>(sw + m);
    float4 swh = *reinterpret_cast<const float4*>(sw + m + HOP);

    // X writes (coalesced: consecutive n -> consecutive j within a segment row)
    if (v0) {
        float4 lo;
        lo.x = xv.x * awl.x; lo.y = xv.y * awl.y;
        lo.z = xv.z * awl.z; lo.w = xv.w * awl.w;
        unsigned off = (b * NSEG + s0) * SEG + m;         // < 2^26
        *reinterpret_cast<float4*>(Xout + off) = lo;
    }
    if (v1) {
        float4 hi;
        hi.x = xv.x * awh.x; hi.y = xv.y * awh.y;
        hi.z = xv.z * awh.z; hi.w = xv.w * awh.w;
        unsigned off = (b * NSEG + (s0 - 1u)) * SEG + (m + HOP);
        *reinterpret_cast<float4*>(Xout + off) = hi;
    }

    // overlap-add collapses to pointwise weight
    float w0 = v0 ? 1.0f : 0.0f;
    float w1 = v1 ? 1.0f : 0.0f;
    float4 r;
    r.x = xv.x * (w0 * awl.x * swl.x + w1 * awh.x * swh.x);
    r.y = xv.y * (w0 * awl.y * swl.y + w1 * awh.y * swh.y);
    r.z = xv.z * (w0 * awl.z * swl.z + w1 * awh.z * swh.z);
    r.w = xv.w * (w0 * awl.w * swl.w + w1 * awh.w * swh.w);
    *reinterpret_cast<float4*>(rec + i) = r;
}

extern "C" void kernel_launch(void* const* d_in, const int* in_sizes, int n_in,
                              void* d_out, int out_size)
{
    const float* x  = (const float*)d_in[0];
    const float* aw = (const float*)d_in[1];
    const float* sw = (const float*)d_in[2];

    float* Xout = (float*)d_out;
    float* rec  = Xout + (size_t)BB * NSEG * SEG;

    const unsigned total_vec4 = (BB * NN) / 4u;           // 8,388,608 (exact multiple)
    const unsigned threads = 512;
    const unsigned blocks = total_vec4 / threads;         // 16384, no remainder

    seg_olap_kernel<<<blocks, threads>>>(x, aw, sw, Xout, rec);
}